// round 14
// baseline (speedup 1.0000x reference)
#include <cuda_runtime.h>
#include <cuda_bf16.h>
#include <cuda_fp16.h>
#include <math.h>
#include <cstdint>

#define S_LEN   1024
#define B_N     4
#define D_MODEL 4096
#define HQ_N    32
#define HKV_N   8
#define HD_N    128
#define MROWS   4096
#define KDIM    4096
#define ATTN_SCALE 0.08838834764831845f

typedef unsigned long long u64;

__device__ __forceinline__ uint32_t smem_u32(const void* p) {
    uint32_t a;
    asm("{ .reg .u64 t; cvta.to.shared.u64 t, %1; cvt.u32.u64 %0, t; }" : "=r"(a) : "l"(p));
    return a;
}
__device__ __forceinline__ void mma_f16(float (&d)[4], const uint32_t (&a)[4],
                                        const uint32_t b0, const uint32_t b1) {
    asm volatile(
        "mma.sync.aligned.m16n8k16.row.col.f32.f16.f16.f32 "
        "{%0,%1,%2,%3}, {%4,%5,%6,%7}, {%8,%9}, {%0,%1,%2,%3};"
        : "+f"(d[0]), "+f"(d[1]), "+f"(d[2]), "+f"(d[3])
        : "r"(a[0]), "r"(a[1]), "r"(a[2]), "r"(a[3]), "r"(b0), "r"(b1));
}
__device__ __forceinline__ void ldm_x4(uint32_t (&r)[4], uint32_t addr) {
    asm volatile("ldmatrix.sync.aligned.m8n8.x4.shared.b16 {%0,%1,%2,%3}, [%4];"
                 : "=r"(r[0]), "=r"(r[1]), "=r"(r[2]), "=r"(r[3]) : "r"(addr));
}
__device__ __forceinline__ void ldm_x4_t(uint32_t (&r)[4], uint32_t addr) {
    asm volatile("ldmatrix.sync.aligned.m8n8.x4.trans.shared.b16 {%0,%1,%2,%3}, [%4];"
                 : "=r"(r[0]), "=r"(r[1]), "=r"(r[2]), "=r"(r[3]) : "r"(addr));
}

// ---------------------------------------------------------------------------
// Scratch
// ---------------------------------------------------------------------------
__device__ float g_Q[(size_t)MROWS * (HQ_N * HD_N)];
__device__ float g_K[(size_t)MROWS * (HKV_N * HD_N)];
__device__ float g_V[(size_t)MROWS * (HKV_N * HD_N)];

__device__ __half g_hid[(size_t)MROWS * D_MODEL];
__device__ __half g_wq[(size_t)4096 * 4096];
__device__ __half g_wk[(size_t)1024 * 4096];
__device__ __half g_wv[(size_t)1024 * 4096];
__device__ __half g_wo[(size_t)4096 * 4096];
__device__ __half g_att[(size_t)MROWS * D_MODEL];
__device__ __half g_kf[(size_t)MROWS * (HKV_N * HD_N)];
__device__ __half g_vf[(size_t)MROWS * (HKV_N * HD_N)];

// ---------------------------------------------------------------------------
// fp32 -> fp16 single
// ---------------------------------------------------------------------------
__global__ void conv_f16(const float* __restrict__ X,
                         __half* __restrict__ H, int n4) {
    int i = blockIdx.x * blockDim.x + threadIdx.x;
    if (i >= n4) return;
    float4 x = *(const float4*)(X + (size_t)i * 4);
    __half2* Hp = (__half2*)(H + (size_t)i * 4);
    Hp[0] = __half2(__float2half_rn(x.x), __float2half_rn(x.y));
    Hp[1] = __half2(__float2half_rn(x.z), __float2half_rn(x.w));
}

// ---------------------------------------------------------------------------
// K/V prep: RoPE K -> fp16, V -> fp16
// ---------------------------------------------------------------------------
__global__ void kv_prep(const float* __restrict__ K, const float* __restrict__ V,
                        const float* __restrict__ cosb, const float* __restrict__ sinb,
                        __half* __restrict__ Kf, __half* __restrict__ Vf) {
    int idx = blockIdx.x * blockDim.x + threadIdx.x;
    if (idx >= MROWS * HKV_N * 64) return;
    int d = idx & 63;
    int h = (idx >> 6) & 7;
    int bs = idx >> 9;
    int s = bs & (S_LEN - 1);
    float c  = cosb[s * HD_N + 64 + d];
    float sn = sinb[s * HD_N + 64 + d];
    size_t base = (size_t)bs * (HKV_N * HD_N) + h * HD_N + d;
    float x1 = K[base], x2 = K[base + 64];
    Kf[base]      = __float2half_rn(x1 * c - x2 * sn);
    Kf[base + 64] = __float2half_rn(x2 * c + x1 * sn);
    Vf[base]      = __float2half_rn(V[base]);
    Vf[base + 64] = __float2half_rn(V[base + 64]);
}

// ---------------------------------------------------------------------------
// fp16 GEMM: C[M][N] = A[M][K] * B[N][K]^T
// 256x128 CTA tile (M=256), 8 warps at 64x64, BK=32, double-buffered.
// ---------------------------------------------------------------------------
#define SROW    80                  // 32 halves + 8 pad = 80 bytes/row
#define ATILE_A (256 * SROW)        // 20480
#define ATILE_B (128 * SROW)        // 10240
#define STAGE   (ATILE_A + ATILE_B) // 30720
#define SM_GEMM (2 * STAGE)         // 61440
#define NCHUNK  (KDIM / 32)         // 128

__global__ void __launch_bounds__(256, 1) gemm_f16(
    const __half* __restrict__ A, const __half* __restrict__ B,
    float* __restrict__ C, int Nn) {
    extern __shared__ char smem[];
    const uint32_t smb = smem_u32(smem);
    const int tid = threadIdx.x;
    const int wid = tid >> 5;
    const int lane = tid & 31;
    const int wm = (wid >> 1) << 6;      // 0,64,128,192
    const int wn = (wid & 1) << 6;       // 0,64
    const int n0 = blockIdx.x << 7;      // 128-wide N tile
    const int m0 = blockIdx.y << 8;      // 256-wide M tile

    const __half* Ap = A + (size_t)m0 * KDIM;
    const __half* Bp = B + (size_t)n0 * KDIM;

    // load slots: row = slot>>2, seg = (slot&3)*8 halves
    int ra[4], sa[4], rb[2], sb2[2];
#pragma unroll
    for (int i = 0; i < 4; i++) {
        int slot = tid + (i << 8);
        ra[i] = slot >> 2;
        sa[i] = (slot & 3) << 3;
    }
#pragma unroll
    for (int i = 0; i < 2; i++) {
        int slot = tid + (i << 8);
        rb[i] = slot >> 2;
        sb2[i] = (slot & 3) << 3;
    }

    float acc[4][8][4];
#pragma unroll
    for (int i = 0; i < 4; i++)
#pragma unroll
        for (int j = 0; j < 8; j++)
#pragma unroll
            for (int t = 0; t < 4; t++) acc[i][j][t] = 0.f;

    // prologue: chunk 0 -> stage 0
    {
        char* dstA = smem;
        char* dstB = smem + ATILE_A;
#pragma unroll
        for (int i = 0; i < 4; i++)
            *(uint4*)(dstA + ra[i] * SROW + (sa[i] << 1)) =
                *(const uint4*)(Ap + (size_t)ra[i] * KDIM + sa[i]);
#pragma unroll
        for (int i = 0; i < 2; i++)
            *(uint4*)(dstB + rb[i] * SROW + (sb2[i] << 1)) =
                *(const uint4*)(Bp + (size_t)rb[i] * KDIM + sb2[i]);
    }
    __syncthreads();

    const uint32_t a_lrow = (lane & 15);
    const uint32_t a_lkh  = (lane >> 4) << 4;
    const uint32_t b_lrow = (lane & 7) + ((lane >> 4) << 3);
    const uint32_t b_lkh  = ((lane >> 3) & 1) << 4;

    uint4 regsA[4];
    uint4 regsB[2];

    for (int c = 0; c < NCHUNK; c++) {
        const int s = c & 1;
        const uint32_t sb = smb + s * STAGE;
        const bool more = (c + 1 < NCHUNK);
        if (more) {
            const int k0 = (c + 1) << 5;
#pragma unroll
            for (int i = 0; i < 4; i++)
                regsA[i] = *(const uint4*)(Ap + (size_t)ra[i] * KDIM + k0 + sa[i]);
#pragma unroll
            for (int i = 0; i < 2; i++)
                regsB[i] = *(const uint4*)(Bp + (size_t)rb[i] * KDIM + k0 + sb2[i]);
        }

#pragma unroll
        for (int ks = 0; ks < 2; ks++) {
            const uint32_t ko = ks << 5;
            uint32_t af[4][4];
#pragma unroll
            for (int i = 0; i < 4; i++) {
                uint32_t rowb = (wm + (i << 4) + a_lrow) * SROW + ko + a_lkh;
                ldm_x4(af[i], sb + rowb);
            }
            uint32_t bf[4][4];
#pragma unroll
            for (int j2 = 0; j2 < 4; j2++) {
                uint32_t rowb = (wn + (j2 << 4) + b_lrow) * SROW + ko + b_lkh;
                ldm_x4(bf[j2], sb + ATILE_A + rowb);
            }
#pragma unroll
            for (int i = 0; i < 4; i++)
#pragma unroll
                for (int j = 0; j < 8; j++) {
                    const uint32_t* bb = &bf[j >> 1][(j & 1) << 1];
                    mma_f16(acc[i][j], af[i], bb[0], bb[1]);
                }
        }

        if (more) {
            const int so = (s ^ 1) * STAGE;
#pragma unroll
            for (int i = 0; i < 4; i++)
                *(uint4*)(smem + so + ra[i] * SROW + (sa[i] << 1)) = regsA[i];
#pragma unroll
            for (int i = 0; i < 2; i++)
                *(uint4*)(smem + so + ATILE_A + rb[i] * SROW + (sb2[i] << 1)) = regsB[i];
        }
        __syncthreads();
    }

    const int erow = m0 + wm + (lane >> 2);
    const int ecol = n0 + wn + ((lane & 3) << 1);
#pragma unroll
    for (int i = 0; i < 4; i++) {
#pragma unroll
        for (int j = 0; j < 8; j++) {
            float* p0 = C + (size_t)(erow + (i << 4)) * Nn + ecol + (j << 3);
            float* p1 = p0 + (size_t)8 * Nn;
            *(float2*)p0 = make_float2(acc[i][j][0], acc[i][j][1]);
            *(float2*)p1 = make_float2(acc[i][j][2], acc[i][j][3]);
        }
    }
}

// ---------------------------------------------------------------------------
// Tensor-core attention (exact R13 version — all single fp16)
// ---------------------------------------------------------------------------
#define QKV_RS 136
#define P_RS   72
#define SM_QF  0
#define SM_KF  17408
#define SM_VF  34816
#define SM_PF  52224
#define SM_RS  61440
#define SM_ATTN (SM_RS + 512)

__global__ void __launch_bounds__(256, 1) attn_tc(
    const float* __restrict__ Q,
    const __half* __restrict__ Kf, const __half* __restrict__ Vf,
    const float* __restrict__ cosb, const float* __restrict__ sinb,
    __half* __restrict__ Oh) {
    extern __shared__ char smem[];
    const uint32_t smb = smem_u32(smem);
    const int tid = threadIdx.x;
    const int wid = tid >> 5;
    const int lane = tid & 31;
    const int b   = blockIdx.x >> 5;
    const int h   = blockIdx.x & 31;
    const int kvh = h >> 2;
    const int q0  = blockIdx.y << 6;

    const uint32_t a_lrow = (lane & 15);
    const uint32_t a_lkh  = (lane >> 4) << 4;
    const uint32_t b_lrow = (lane & 7) + ((lane >> 4) << 3);
    const uint32_t b_lkh  = ((lane >> 3) & 1) << 4;
    const int wq = (wid & 3) << 4;
    const int wk = (wid >> 2) << 5;

#pragma unroll
    for (int it = 0; it < 4; it++) {
        int slot = tid + (it << 8);
        int r = slot >> 4;
        int d = (slot & 15) << 2;
        int srow = q0 + r;
        const float* src = Q + ((size_t)(b * S_LEN + srow)) * (HQ_N * HD_N) + h * HD_N + d;
        float4 x1 = *(const float4*)(src);
        float4 x2 = *(const float4*)(src + 64);
        float4 cs = *(const float4*)(cosb + srow * HD_N + 64 + d);
        float4 sn = *(const float4*)(sinb + srow * HD_N + 64 + d);
        __half* qf = (__half*)(smem + SM_QF) + r * QKV_RS;
        qf[d + 0] = __float2half_rn((x1.x * cs.x - x2.x * sn.x) * ATTN_SCALE);
        qf[d + 1] = __float2half_rn((x1.y * cs.y - x2.y * sn.y) * ATTN_SCALE);
        qf[d + 2] = __float2half_rn((x1.z * cs.z - x2.z * sn.z) * ATTN_SCALE);
        qf[d + 3] = __float2half_rn((x1.w * cs.w - x2.w * sn.w) * ATTN_SCALE);
        qf[d + 64] = __float2half_rn((x2.x * cs.x + x1.x * sn.x) * ATTN_SCALE);
        qf[d + 65] = __float2half_rn((x2.y * cs.y + x1.y * sn.y) * ATTN_SCALE);
        qf[d + 66] = __float2half_rn((x2.z * cs.z + x1.z * sn.z) * ATTN_SCALE);
        qf[d + 67] = __float2half_rn((x2.w * cs.w + x1.w * sn.w) * ATTN_SCALE);
    }

    float oacc[4][2][4];
#pragma unroll
    for (int i = 0; i < 4; i++)
#pragma unroll
        for (int j = 0; j < 2; j++)
#pragma unroll
            for (int t = 0; t < 4; t++) oacc[i][j][t] = 0.f;
    float rs0 = 0.f, rs1 = 0.f;

    const __half* kvsrc[2] = { Kf, Vf };
    const uint32_t kvdst[2] = { SM_KF, SM_VF };

    for (int kt = 0; kt < S_LEN; kt += 64) {
        __syncthreads();

#pragma unroll
        for (int arr = 0; arr < 2; arr++) {
            const __half* src = kvsrc[arr]
                + ((size_t)(b * S_LEN + kt)) * (HKV_N * HD_N) + kvh * HD_N;
            char* dst = smem + kvdst[arr];
#pragma unroll
            for (int it = 0; it < 4; it++) {
                int slot = tid + (it << 8);
                int r = slot >> 4;
                int cs = slot & 15;
                *(uint4*)(dst + r * (QKV_RS * 2) + (cs << 4)) =
                    *(const uint4*)(src + (size_t)r * (HKV_N * HD_N) + (cs << 3));
            }
        }
        __syncthreads();

        float sacc[4][4];
#pragma unroll
        for (int i = 0; i < 4; i++)
#pragma unroll
            for (int t = 0; t < 4; t++) sacc[i][t] = 0.f;

#pragma unroll
        for (int ks = 0; ks < 8; ks++) {
            const uint32_t ko = ks << 5;
            uint32_t aq[4];
            {
                uint32_t rowb = (wq + a_lrow) * (QKV_RS * 2) + ko + a_lkh;
                ldm_x4(aq, smb + SM_QF + rowb);
            }
            uint32_t bk[2][4];
#pragma unroll
            for (int g = 0; g < 2; g++) {
                uint32_t rowb = (wk + (g << 4) + b_lrow) * (QKV_RS * 2) + ko + b_lkh;
                ldm_x4(bk[g], smb + SM_KF + rowb);
            }
#pragma unroll
            for (int g = 0; g < 2; g++)
#pragma unroll
                for (int sub = 0; sub < 2; sub++) {
                    int nidx = (g << 1) + sub;
                    const uint32_t* kk = &bk[g][sub << 1];
                    mma_f16(sacc[nidx], aq, kk[0], kk[1]);
                }
        }

        float ps0 = 0.f, ps1 = 0.f;
        const int prow0 = wq + (lane >> 2);
#pragma unroll
        for (int f = 0; f < 4; f++) {
            float p0 = __expf(sacc[f][0]);
            float p1 = __expf(sacc[f][1]);
            float p2 = __expf(sacc[f][2]);
            float p3 = __expf(sacc[f][3]);
            ps0 += p0 + p1;
            ps1 += p2 + p3;
            int col = wk + (f << 3) + ((lane & 3) << 1);
            *(__half2*)((__half*)(smem + SM_PF) + prow0 * P_RS + col) =
                __half2(__float2half_rn(p0), __float2half_rn(p1));
            *(__half2*)((__half*)(smem + SM_PF) + (prow0 + 8) * P_RS + col) =
                __half2(__float2half_rn(p2), __float2half_rn(p3));
        }
        ps0 += __shfl_xor_sync(0xFFFFFFFF, ps0, 1);
        ps0 += __shfl_xor_sync(0xFFFFFFFF, ps0, 2);
        ps1 += __shfl_xor_sync(0xFFFFFFFF, ps1, 1);
        ps1 += __shfl_xor_sync(0xFFFFFFFF, ps1, 2);
        rs0 += ps0;
        rs1 += ps1;
        __syncthreads();

        const int nb = wid << 4;
#pragma unroll
        for (int ks = 0; ks < 4; ks++) {
            uint32_t vbf[4];
            {
                uint32_t rowb = ((ks << 4) + (lane & 15)) * (QKV_RS * 2) + ((nb + ((lane >> 4) << 3)) << 1);
                ldm_x4_t(vbf, smb + SM_VF + rowb);
            }
#pragma unroll
            for (int mt = 0; mt < 4; mt++) {
                uint32_t pf[4];
                uint32_t rowb = ((mt << 4) + a_lrow) * (P_RS * 2) + (ks << 5) + a_lkh;
                ldm_x4(pf, smb + SM_PF + rowb);
#pragma unroll
                for (int sub = 0; sub < 2; sub++) {
                    const uint32_t* vv = &vbf[sub << 1];
                    mma_f16(oacc[mt][sub], pf, vv[0], vv[1]);
                }
            }
        }
    }

    float* rssm = (float*)(smem + SM_RS);
    if ((lane & 3) == 0) {
        rssm[((wid >> 2) << 6) + wq + (lane >> 2)] = rs0;
        rssm[((wid >> 2) << 6) + wq + (lane >> 2) + 8] = rs1;
    }
    __syncthreads();

#pragma unroll
    for (int mt = 0; mt < 4; mt++) {
        int r0 = (mt << 4) + (lane >> 2);
        int r1 = r0 + 8;
        float inv0 = 1.0f / (rssm[r0] + rssm[64 + r0]);
        float inv1 = 1.0f / (rssm[r1] + rssm[64 + r1]);
#pragma unroll
        for (int sub = 0; sub < 2; sub++) {
            int col = (wid << 4) + (sub << 3) + ((lane & 3) << 1);
            float v00 = oacc[mt][sub][0] * inv0;
            float v01 = oacc[mt][sub][1] * inv0;
            float v10 = oacc[mt][sub][2] * inv1;
            float v11 = oacc[mt][sub][3] * inv1;
            size_t base0 = ((size_t)(b * S_LEN + q0 + r0)) * D_MODEL + h * HD_N + col;
            size_t base1 = ((size_t)(b * S_LEN + q0 + r1)) * D_MODEL + h * HD_N + col;
            *(__half2*)(Oh + base0) = __half2(__float2half_rn(v00), __float2half_rn(v01));
            *(__half2*)(Oh + base1) = __half2(__float2half_rn(v10), __float2half_rn(v11));
        }
    }
}

// ---------------------------------------------------------------------------
// Launch
// ---------------------------------------------------------------------------
extern "C" void kernel_launch(void* const* d_in, const int* in_sizes, int n_in,
                              void* d_out, int out_size) {
    const float* hidden = (const float*)d_in[0];
    const float* cosb   = (const float*)d_in[1];
    const float* sinb   = (const float*)d_in[2];
    const float* Wq     = (const float*)d_in[3];
    const float* Wk     = (const float*)d_in[4];
    const float* Wv     = (const float*)d_in[5];
    const float* Wo     = (const float*)d_in[6];
    float* out = (float*)d_out;

    float *pQ, *pK, *pV;
    cudaGetSymbolAddress((void**)&pQ, g_Q);
    cudaGetSymbolAddress((void**)&pK, g_K);
    cudaGetSymbolAddress((void**)&pV, g_V);

    __half *hid, *wq, *wk, *wv, *wo, *att, *pkf, *pvf;
    cudaGetSymbolAddress((void**)&hid, g_hid);
    cudaGetSymbolAddress((void**)&wq, g_wq);   cudaGetSymbolAddress((void**)&wk, g_wk);
    cudaGetSymbolAddress((void**)&wv, g_wv);   cudaGetSymbolAddress((void**)&wo, g_wo);
    cudaGetSymbolAddress((void**)&att, g_att);
    cudaGetSymbolAddress((void**)&pkf, g_kf);  cudaGetSymbolAddress((void**)&pvf, g_vf);

    const int n_big   = 4096 * 4096 / 4;
    const int n_small = 1024 * 4096 / 4;
    conv_f16<<<(n_big + 255) / 256, 256>>>(hidden, hid, n_big);
    conv_f16<<<(n_big + 255) / 256, 256>>>(Wq, wq, n_big);
    conv_f16<<<(n_small + 255) / 256, 256>>>(Wk, wk, n_small);
    conv_f16<<<(n_small + 255) / 256, 256>>>(Wv, wv, n_small);
    conv_f16<<<(n_big + 255) / 256, 256>>>(Wo, wo, n_big);

    cudaFuncSetAttribute(gemm_f16, cudaFuncAttributeMaxDynamicSharedMemorySize, SM_GEMM);
    gemm_f16<<<dim3(32, 16), 256, SM_GEMM>>>(hid, wq, pQ, 4096);
    gemm_f16<<<dim3(8, 16),  256, SM_GEMM>>>(hid, wk, pK, 1024);
    gemm_f16<<<dim3(8, 16),  256, SM_GEMM>>>(hid, wv, pV, 1024);

    {
        int tot = MROWS * HKV_N * 64;
        kv_prep<<<(tot + 255) / 256, 256>>>(pK, pV, cosb, sinb, pkf, pvf);
    }

    cudaFuncSetAttribute(attn_tc, cudaFuncAttributeMaxDynamicSharedMemorySize, SM_ATTN);
    attn_tc<<<dim3(B_N * HQ_N, S_LEN / 64), 256, SM_ATTN>>>(
        pQ, pkf, pvf, cosb, sinb, att);

    gemm_f16<<<dim3(32, 16), 256, SM_GEMM>>>(att, wo, out, 4096);
}

// round 15
// speedup vs baseline: 1.1573x; 1.1573x over previous
#include <cuda_runtime.h>
#include <cuda_bf16.h>
#include <cuda_fp16.h>
#include <math.h>
#include <cstdint>

#define S_LEN   1024
#define B_N     4
#define D_MODEL 4096
#define HQ_N    32
#define HKV_N   8
#define HD_N    128
#define MROWS   4096
#define KDIM    4096
#define ATTN_SCALE 0.08838834764831845f

typedef unsigned long long u64;

__device__ __forceinline__ uint32_t smem_u32(const void* p) {
    uint32_t a;
    asm("{ .reg .u64 t; cvta.to.shared.u64 t, %1; cvt.u32.u64 %0, t; }" : "=r"(a) : "l"(p));
    return a;
}
__device__ __forceinline__ void mma_f16(float (&d)[4], const uint32_t (&a)[4],
                                        const uint32_t b0, const uint32_t b1) {
    asm volatile(
        "mma.sync.aligned.m16n8k16.row.col.f32.f16.f16.f32 "
        "{%0,%1,%2,%3}, {%4,%5,%6,%7}, {%8,%9}, {%0,%1,%2,%3};"
        : "+f"(d[0]), "+f"(d[1]), "+f"(d[2]), "+f"(d[3])
        : "r"(a[0]), "r"(a[1]), "r"(a[2]), "r"(a[3]), "r"(b0), "r"(b1));
}
__device__ __forceinline__ void ldm_x4(uint32_t (&r)[4], uint32_t addr) {
    asm volatile("ldmatrix.sync.aligned.m8n8.x4.shared.b16 {%0,%1,%2,%3}, [%4];"
                 : "=r"(r[0]), "=r"(r[1]), "=r"(r[2]), "=r"(r[3]) : "r"(addr));
}
__device__ __forceinline__ void ldm_x4_t(uint32_t (&r)[4], uint32_t addr) {
    asm volatile("ldmatrix.sync.aligned.m8n8.x4.trans.shared.b16 {%0,%1,%2,%3}, [%4];"
                 : "=r"(r[0]), "=r"(r[1]), "=r"(r[2]), "=r"(r[3]) : "r"(addr));
}

// ---------------------------------------------------------------------------
// Scratch
// ---------------------------------------------------------------------------
__device__ float g_Q[(size_t)MROWS * (HQ_N * HD_N)];
__device__ float g_K[(size_t)MROWS * (HKV_N * HD_N)];
__device__ float g_V[(size_t)MROWS * (HKV_N * HD_N)];

__device__ __half g_hid[(size_t)MROWS * D_MODEL];
__device__ __half g_wq[(size_t)4096 * 4096];
__device__ __half g_wk[(size_t)1024 * 4096];
__device__ __half g_wv[(size_t)1024 * 4096];
__device__ __half g_wo[(size_t)4096 * 4096];
__device__ __half g_att[(size_t)MROWS * D_MODEL];
__device__ __half g_kf[(size_t)MROWS * (HKV_N * HD_N)];
__device__ __half g_vf[(size_t)MROWS * (HKV_N * HD_N)];

// ---------------------------------------------------------------------------
// fused fp32 -> fp16 conversion over 5 segments
// segments: hidden(16.78M), Wq(16.78M), Wk(4.19M), Wv(4.19M), Wo(16.78M)
// ---------------------------------------------------------------------------
#define SEG_BIG   (4096 * 4096 / 4)
#define SEG_SMALL (1024 * 4096 / 4)
#define N4_TOTAL  (3 * SEG_BIG + 2 * SEG_SMALL)

__global__ void conv_all_f16(const float* __restrict__ X0, __half* __restrict__ H0,
                             const float* __restrict__ X1, __half* __restrict__ H1,
                             const float* __restrict__ X2, __half* __restrict__ H2,
                             const float* __restrict__ X3, __half* __restrict__ H3,
                             const float* __restrict__ X4, __half* __restrict__ H4) {
    int i = blockIdx.x * blockDim.x + threadIdx.x;
    if (i >= N4_TOTAL) return;
    const float* X;
    __half* H;
    int off = i;
    if (off < SEG_BIG)                    { X = X0; H = H0; }
    else if ((off -= SEG_BIG) < SEG_BIG)  { X = X1; H = H1; }
    else if ((off -= SEG_BIG) < SEG_SMALL){ X = X2; H = H2; }
    else if ((off -= SEG_SMALL) < SEG_SMALL){ X = X3; H = H3; }
    else { off -= SEG_SMALL; X = X4; H = H4; }
    float4 x = *(const float4*)(X + (size_t)off * 4);
    __half2* Hp = (__half2*)(H + (size_t)off * 4);
    Hp[0] = __half2(__float2half_rn(x.x), __float2half_rn(x.y));
    Hp[1] = __half2(__float2half_rn(x.z), __float2half_rn(x.w));
}

// ---------------------------------------------------------------------------
// K/V prep: RoPE K -> fp16, V -> fp16
// ---------------------------------------------------------------------------
__global__ void kv_prep(const float* __restrict__ K, const float* __restrict__ V,
                        const float* __restrict__ cosb, const float* __restrict__ sinb,
                        __half* __restrict__ Kf, __half* __restrict__ Vf) {
    int idx = blockIdx.x * blockDim.x + threadIdx.x;
    if (idx >= MROWS * HKV_N * 64) return;
    int d = idx & 63;
    int h = (idx >> 6) & 7;
    int bs = idx >> 9;
    int s = bs & (S_LEN - 1);
    float c  = cosb[s * HD_N + 64 + d];
    float sn = sinb[s * HD_N + 64 + d];
    size_t base = (size_t)bs * (HKV_N * HD_N) + h * HD_N + d;
    float x1 = K[base], x2 = K[base + 64];
    Kf[base]      = __float2half_rn(x1 * c - x2 * sn);
    Kf[base + 64] = __float2half_rn(x2 * c + x1 * sn);
    Vf[base]      = __float2half_rn(V[base]);
    Vf[base + 64] = __float2half_rn(V[base + 64]);
}

// ---------------------------------------------------------------------------
// fp16 GEMM body (R13-exact): 128x128 tile, BK=64, double-buffered
// ---------------------------------------------------------------------------
#define SROW   144
#define ATILE  (128 * SROW)
#define STAGE  (2 * ATILE)
#define SM_GEMM (2 * STAGE)
#define NCHUNK (KDIM / 64)

__device__ __forceinline__ void gemm_body(
    const __half* __restrict__ A, const __half* __restrict__ B,
    float* __restrict__ C, int Nn, int m0, int n0, char* smem) {
    const uint32_t smb = smem_u32(smem);
    const int tid = threadIdx.x;
    const int wid = tid >> 5;
    const int lane = tid & 31;
    const int wm = (wid >> 2) << 6;
    const int wn = (wid & 3) << 5;

    const __half* srcs[2] = { A + (size_t)m0 * KDIM, B + (size_t)n0 * KDIM };

    int r_ld[4], sseg[4];
#pragma unroll
    for (int i = 0; i < 4; i++) {
        int slot = tid + (i << 8);
        r_ld[i] = slot >> 3;
        sseg[i] = (slot & 7) << 3;
    }

    float acc[4][4][4];
#pragma unroll
    for (int i = 0; i < 4; i++)
#pragma unroll
        for (int j = 0; j < 4; j++)
#pragma unroll
            for (int t = 0; t < 4; t++) acc[i][j][t] = 0.f;

#pragma unroll
    for (int arr = 0; arr < 2; arr++) {
        char* dst = smem + arr * ATILE;
        const __half* src = srcs[arr];
#pragma unroll
        for (int i = 0; i < 4; i++)
            *(uint4*)(dst + r_ld[i] * SROW + (sseg[i] << 1)) =
                *(const uint4*)(src + (size_t)r_ld[i] * KDIM + sseg[i]);
    }
    __syncthreads();

    const uint32_t a_lrow = (lane & 15);
    const uint32_t a_lkh  = (lane >> 4) << 4;
    const uint32_t b_lrow = (lane & 7) + ((lane >> 4) << 3);
    const uint32_t b_lkh  = ((lane >> 3) & 1) << 4;

    uint4 regs[8];

    for (int c = 0; c < NCHUNK; c++) {
        const int s = c & 1;
        const uint32_t sb = smb + s * STAGE;
        const bool more = (c + 1 < NCHUNK);
        if (more) {
            const int k0 = (c + 1) << 6;
#pragma unroll
            for (int arr = 0; arr < 2; arr++)
#pragma unroll
                for (int i = 0; i < 4; i++)
                    regs[arr * 4 + i] =
                        *(const uint4*)(srcs[arr] + (size_t)r_ld[i] * KDIM + k0 + sseg[i]);
        }

#pragma unroll
        for (int ks = 0; ks < 4; ks++) {
            const uint32_t ko = ks << 5;
            uint32_t af[4][4];
#pragma unroll
            for (int i = 0; i < 4; i++) {
                uint32_t rowb = (wm + (i << 4) + a_lrow) * SROW + ko + a_lkh;
                ldm_x4(af[i], sb + 0 * ATILE + rowb);
            }
            uint32_t bf[2][4];
#pragma unroll
            for (int j2 = 0; j2 < 2; j2++) {
                uint32_t rowb = (wn + (j2 << 4) + b_lrow) * SROW + ko + b_lkh;
                ldm_x4(bf[j2], sb + 1 * ATILE + rowb);
            }
#pragma unroll
            for (int i = 0; i < 4; i++)
#pragma unroll
                for (int j = 0; j < 4; j++) {
                    const uint32_t* bb = &bf[j >> 1][(j & 1) << 1];
                    mma_f16(acc[i][j], af[i], bb[0], bb[1]);
                }
        }

        if (more) {
            const int so = (s ^ 1) * STAGE;
#pragma unroll
            for (int arr = 0; arr < 2; arr++)
#pragma unroll
                for (int i = 0; i < 4; i++)
                    *(uint4*)(smem + so + arr * ATILE + r_ld[i] * SROW + (sseg[i] << 1)) =
                        regs[arr * 4 + i];
        }
        __syncthreads();
    }

    const int erow = m0 + wm + (lane >> 2);
    const int ecol = n0 + wn + ((lane & 3) << 1);
#pragma unroll
    for (int i = 0; i < 4; i++) {
#pragma unroll
        for (int j = 0; j < 4; j++) {
            float* p0 = C + (size_t)(erow + (i << 4)) * Nn + ecol + (j << 3);
            float* p1 = p0 + (size_t)8 * Nn;
            *(float2*)p0 = make_float2(acc[i][j][0], acc[i][j][1]);
            *(float2*)p1 = make_float2(acc[i][j][2], acc[i][j][3]);
        }
    }
}

// Fused QKV projection: grid.x covers [Q:32 | K:8 | V:8] N-tiles
__global__ void __launch_bounds__(256, 1) gemm_qkv(
    const __half* __restrict__ hid,
    const __half* __restrict__ Wq, const __half* __restrict__ Wk,
    const __half* __restrict__ Wv,
    float* __restrict__ Cq, float* __restrict__ Ck, float* __restrict__ Cv) {
    extern __shared__ char smem[];
    const int nt = blockIdx.x;
    const int m0 = blockIdx.y << 7;
    const __half* B;
    float* C;
    int Nn, n0;
    if (nt < 32)      { B = Wq; C = Cq; Nn = 4096; n0 = nt << 7; }
    else if (nt < 40) { B = Wk; C = Ck; Nn = 1024; n0 = (nt - 32) << 7; }
    else              { B = Wv; C = Cv; Nn = 1024; n0 = (nt - 40) << 7; }
    gemm_body(hid, B, C, Nn, m0, n0, smem);
}

// Single GEMM (output projection)
__global__ void __launch_bounds__(256, 1) gemm_f16(
    const __half* __restrict__ A, const __half* __restrict__ B,
    float* __restrict__ C, int Nn) {
    extern __shared__ char smem[];
    gemm_body(A, B, C, Nn, blockIdx.y << 7, blockIdx.x << 7, smem);
}

// ---------------------------------------------------------------------------
// Tensor-core attention (exact R13 version — all single fp16)
// ---------------------------------------------------------------------------
#define QKV_RS 136
#define P_RS   72
#define SM_QF  0
#define SM_KF  17408
#define SM_VF  34816
#define SM_PF  52224
#define SM_RS  61440
#define SM_ATTN (SM_RS + 512)

__global__ void __launch_bounds__(256, 1) attn_tc(
    const float* __restrict__ Q,
    const __half* __restrict__ Kf, const __half* __restrict__ Vf,
    const float* __restrict__ cosb, const float* __restrict__ sinb,
    __half* __restrict__ Oh) {
    extern __shared__ char smem[];
    const uint32_t smb = smem_u32(smem);
    const int tid = threadIdx.x;
    const int wid = tid >> 5;
    const int lane = tid & 31;
    const int b   = blockIdx.x >> 5;
    const int h   = blockIdx.x & 31;
    const int kvh = h >> 2;
    const int q0  = blockIdx.y << 6;

    const uint32_t a_lrow = (lane & 15);
    const uint32_t a_lkh  = (lane >> 4) << 4;
    const uint32_t b_lrow = (lane & 7) + ((lane >> 4) << 3);
    const uint32_t b_lkh  = ((lane >> 3) & 1) << 4;
    const int wq = (wid & 3) << 4;
    const int wk = (wid >> 2) << 5;

#pragma unroll
    for (int it = 0; it < 4; it++) {
        int slot = tid + (it << 8);
        int r = slot >> 4;
        int d = (slot & 15) << 2;
        int srow = q0 + r;
        const float* src = Q + ((size_t)(b * S_LEN + srow)) * (HQ_N * HD_N) + h * HD_N + d;
        float4 x1 = *(const float4*)(src);
        float4 x2 = *(const float4*)(src + 64);
        float4 cs = *(const float4*)(cosb + srow * HD_N + 64 + d);
        float4 sn = *(const float4*)(sinb + srow * HD_N + 64 + d);
        __half* qf = (__half*)(smem + SM_QF) + r * QKV_RS;
        qf[d + 0] = __float2half_rn((x1.x * cs.x - x2.x * sn.x) * ATTN_SCALE);
        qf[d + 1] = __float2half_rn((x1.y * cs.y - x2.y * sn.y) * ATTN_SCALE);
        qf[d + 2] = __float2half_rn((x1.z * cs.z - x2.z * sn.z) * ATTN_SCALE);
        qf[d + 3] = __float2half_rn((x1.w * cs.w - x2.w * sn.w) * ATTN_SCALE);
        qf[d + 64] = __float2half_rn((x2.x * cs.x + x1.x * sn.x) * ATTN_SCALE);
        qf[d + 65] = __float2half_rn((x2.y * cs.y + x1.y * sn.y) * ATTN_SCALE);
        qf[d + 66] = __float2half_rn((x2.z * cs.z + x1.z * sn.z) * ATTN_SCALE);
        qf[d + 67] = __float2half_rn((x2.w * cs.w + x1.w * sn.w) * ATTN_SCALE);
    }

    float oacc[4][2][4];
#pragma unroll
    for (int i = 0; i < 4; i++)
#pragma unroll
        for (int j = 0; j < 2; j++)
#pragma unroll
            for (int t = 0; t < 4; t++) oacc[i][j][t] = 0.f;
    float rs0 = 0.f, rs1 = 0.f;

    const __half* kvsrc[2] = { Kf, Vf };
    const uint32_t kvdst[2] = { SM_KF, SM_VF };

    for (int kt = 0; kt < S_LEN; kt += 64) {
        __syncthreads();

#pragma unroll
        for (int arr = 0; arr < 2; arr++) {
            const __half* src = kvsrc[arr]
                + ((size_t)(b * S_LEN + kt)) * (HKV_N * HD_N) + kvh * HD_N;
            char* dst = smem + kvdst[arr];
#pragma unroll
            for (int it = 0; it < 4; it++) {
                int slot = tid + (it << 8);
                int r = slot >> 4;
                int cs = slot & 15;
                *(uint4*)(dst + r * (QKV_RS * 2) + (cs << 4)) =
                    *(const uint4*)(src + (size_t)r * (HKV_N * HD_N) + (cs << 3));
            }
        }
        __syncthreads();

        float sacc[4][4];
#pragma unroll
        for (int i = 0; i < 4; i++)
#pragma unroll
            for (int t = 0; t < 4; t++) sacc[i][t] = 0.f;

#pragma unroll
        for (int ks = 0; ks < 8; ks++) {
            const uint32_t ko = ks << 5;
            uint32_t aq[4];
            {
                uint32_t rowb = (wq + a_lrow) * (QKV_RS * 2) + ko + a_lkh;
                ldm_x4(aq, smb + SM_QF + rowb);
            }
            uint32_t bk[2][4];
#pragma unroll
            for (int g = 0; g < 2; g++) {
                uint32_t rowb = (wk + (g << 4) + b_lrow) * (QKV_RS * 2) + ko + b_lkh;
                ldm_x4(bk[g], smb + SM_KF + rowb);
            }
#pragma unroll
            for (int g = 0; g < 2; g++)
#pragma unroll
                for (int sub = 0; sub < 2; sub++) {
                    int nidx = (g << 1) + sub;
                    const uint32_t* kk = &bk[g][sub << 1];
                    mma_f16(sacc[nidx], aq, kk[0], kk[1]);
                }
        }

        float ps0 = 0.f, ps1 = 0.f;
        const int prow0 = wq + (lane >> 2);
#pragma unroll
        for (int f = 0; f < 4; f++) {
            float p0 = __expf(sacc[f][0]);
            float p1 = __expf(sacc[f][1]);
            float p2 = __expf(sacc[f][2]);
            float p3 = __expf(sacc[f][3]);
            ps0 += p0 + p1;
            ps1 += p2 + p3;
            int col = wk + (f << 3) + ((lane & 3) << 1);
            *(__half2*)((__half*)(smem + SM_PF) + prow0 * P_RS + col) =
                __half2(__float2half_rn(p0), __float2half_rn(p1));
            *(__half2*)((__half*)(smem + SM_PF) + (prow0 + 8) * P_RS + col) =
                __half2(__float2half_rn(p2), __float2half_rn(p3));
        }
        ps0 += __shfl_xor_sync(0xFFFFFFFF, ps0, 1);
        ps0 += __shfl_xor_sync(0xFFFFFFFF, ps0, 2);
        ps1 += __shfl_xor_sync(0xFFFFFFFF, ps1, 1);
        ps1 += __shfl_xor_sync(0xFFFFFFFF, ps1, 2);
        rs0 += ps0;
        rs1 += ps1;
        __syncthreads();

        const int nb = wid << 4;
#pragma unroll
        for (int ks = 0; ks < 4; ks++) {
            uint32_t vbf[4];
            {
                uint32_t rowb = ((ks << 4) + (lane & 15)) * (QKV_RS * 2) + ((nb + ((lane >> 4) << 3)) << 1);
                ldm_x4_t(vbf, smb + SM_VF + rowb);
            }
#pragma unroll
            for (int mt = 0; mt < 4; mt++) {
                uint32_t pf[4];
                uint32_t rowb = ((mt << 4) + a_lrow) * (P_RS * 2) + (ks << 5) + a_lkh;
                ldm_x4(pf, smb + SM_PF + rowb);
#pragma unroll
                for (int sub = 0; sub < 2; sub++) {
                    const uint32_t* vv = &vbf[sub << 1];
                    mma_f16(oacc[mt][sub], pf, vv[0], vv[1]);
                }
            }
        }
    }

    float* rssm = (float*)(smem + SM_RS);
    if ((lane & 3) == 0) {
        rssm[((wid >> 2) << 6) + wq + (lane >> 2)] = rs0;
        rssm[((wid >> 2) << 6) + wq + (lane >> 2) + 8] = rs1;
    }
    __syncthreads();

#pragma unroll
    for (int mt = 0; mt < 4; mt++) {
        int r0 = (mt << 4) + (lane >> 2);
        int r1 = r0 + 8;
        float inv0 = 1.0f / (rssm[r0] + rssm[64 + r0]);
        float inv1 = 1.0f / (rssm[r1] + rssm[64 + r1]);
#pragma unroll
        for (int sub = 0; sub < 2; sub++) {
            int col = (wid << 4) + (sub << 3) + ((lane & 3) << 1);
            float v00 = oacc[mt][sub][0] * inv0;
            float v01 = oacc[mt][sub][1] * inv0;
            float v10 = oacc[mt][sub][2] * inv1;
            float v11 = oacc[mt][sub][3] * inv1;
            size_t base0 = ((size_t)(b * S_LEN + q0 + r0)) * D_MODEL + h * HD_N + col;
            size_t base1 = ((size_t)(b * S_LEN + q0 + r1)) * D_MODEL + h * HD_N + col;
            *(__half2*)(Oh + base0) = __half2(__float2half_rn(v00), __float2half_rn(v01));
            *(__half2*)(Oh + base1) = __half2(__float2half_rn(v10), __float2half_rn(v11));
        }
    }
}

// ---------------------------------------------------------------------------
// Launch
// ---------------------------------------------------------------------------
extern "C" void kernel_launch(void* const* d_in, const int* in_sizes, int n_in,
                              void* d_out, int out_size) {
    const float* hidden = (const float*)d_in[0];
    const float* cosb   = (const float*)d_in[1];
    const float* sinb   = (const float*)d_in[2];
    const float* Wq     = (const float*)d_in[3];
    const float* Wk     = (const float*)d_in[4];
    const float* Wv     = (const float*)d_in[5];
    const float* Wo     = (const float*)d_in[6];
    float* out = (float*)d_out;

    float *pQ, *pK, *pV;
    cudaGetSymbolAddress((void**)&pQ, g_Q);
    cudaGetSymbolAddress((void**)&pK, g_K);
    cudaGetSymbolAddress((void**)&pV, g_V);

    __half *hid, *wq, *wk, *wv, *wo, *att, *pkf, *pvf;
    cudaGetSymbolAddress((void**)&hid, g_hid);
    cudaGetSymbolAddress((void**)&wq, g_wq);   cudaGetSymbolAddress((void**)&wk, g_wk);
    cudaGetSymbolAddress((void**)&wv, g_wv);   cudaGetSymbolAddress((void**)&wo, g_wo);
    cudaGetSymbolAddress((void**)&att, g_att);
    cudaGetSymbolAddress((void**)&pkf, g_kf);  cudaGetSymbolAddress((void**)&pvf, g_vf);

    // fused conversions
    conv_all_f16<<<(N4_TOTAL + 255) / 256, 256>>>(
        hidden, hid, Wq, wq, Wk, wk, Wv, wv, Wo, wo);

    // fused QKV projection
    cudaFuncSetAttribute(gemm_qkv, cudaFuncAttributeMaxDynamicSharedMemorySize, SM_GEMM);
    cudaFuncSetAttribute(gemm_f16, cudaFuncAttributeMaxDynamicSharedMemorySize, SM_GEMM);
    gemm_qkv<<<dim3(48, 32), 256, SM_GEMM>>>(hid, wq, wk, wv, pQ, pK, pV);

    {
        int tot = MROWS * HKV_N * 64;
        kv_prep<<<(tot + 255) / 256, 256>>>(pK, pV, cosb, sinb, pkf, pvf);
    }

    cudaFuncSetAttribute(attn_tc, cudaFuncAttributeMaxDynamicSharedMemorySize, SM_ATTN);
    attn_tc<<<dim3(B_N * HQ_N, S_LEN / 64), 256, SM_ATTN>>>(
        pQ, pkf, pvf, cosb, sinb, att);

    gemm_f16<<<dim3(32, 32), 256, SM_GEMM>>>(att, wo, out, 4096);
}

// round 16
// speedup vs baseline: 1.2308x; 1.0635x over previous
#include <cuda_runtime.h>
#include <cuda_bf16.h>
#include <cuda_fp16.h>
#include <math.h>
#include <cstdint>

#define S_LEN   1024
#define B_N     4
#define D_MODEL 4096
#define HQ_N    32
#define HKV_N   8
#define HD_N    128
#define MROWS   4096
#define KDIM    4096
#define ATTN_SCALE 0.08838834764831845f

typedef unsigned long long u64;

__device__ __forceinline__ uint32_t smem_u32(const void* p) {
    uint32_t a;
    asm("{ .reg .u64 t; cvta.to.shared.u64 t, %1; cvt.u32.u64 %0, t; }" : "=r"(a) : "l"(p));
    return a;
}
__device__ __forceinline__ void mma_f16(float (&d)[4], const uint32_t (&a)[4],
                                        const uint32_t b0, const uint32_t b1) {
    asm volatile(
        "mma.sync.aligned.m16n8k16.row.col.f32.f16.f16.f32 "
        "{%0,%1,%2,%3}, {%4,%5,%6,%7}, {%8,%9}, {%0,%1,%2,%3};"
        : "+f"(d[0]), "+f"(d[1]), "+f"(d[2]), "+f"(d[3])
        : "r"(a[0]), "r"(a[1]), "r"(a[2]), "r"(a[3]), "r"(b0), "r"(b1));
}
__device__ __forceinline__ void ldm_x4(uint32_t (&r)[4], uint32_t addr) {
    asm volatile("ldmatrix.sync.aligned.m8n8.x4.shared.b16 {%0,%1,%2,%3}, [%4];"
                 : "=r"(r[0]), "=r"(r[1]), "=r"(r[2]), "=r"(r[3]) : "r"(addr));
}
__device__ __forceinline__ void ldm_x4_t(uint32_t (&r)[4], uint32_t addr) {
    asm volatile("ldmatrix.sync.aligned.m8n8.x4.trans.shared.b16 {%0,%1,%2,%3}, [%4];"
                 : "=r"(r[0]), "=r"(r[1]), "=r"(r[2]), "=r"(r[3]) : "r"(addr));
}

// ---------------------------------------------------------------------------
// Scratch
// ---------------------------------------------------------------------------
__device__ float g_Q[(size_t)MROWS * (HQ_N * HD_N)];
__device__ float g_K[(size_t)MROWS * (HKV_N * HD_N)];
__device__ float g_V[(size_t)MROWS * (HKV_N * HD_N)];

__device__ __half g_hid[(size_t)MROWS * D_MODEL];
__device__ __half g_wq[(size_t)4096 * 4096];
__device__ __half g_wk[(size_t)1024 * 4096];
__device__ __half g_wv[(size_t)1024 * 4096];
__device__ __half g_wo[(size_t)4096 * 4096];
__device__ __half g_att[(size_t)MROWS * D_MODEL];
__device__ __half g_kf[(size_t)MROWS * (HKV_N * HD_N)];
__device__ __half g_vf[(size_t)MROWS * (HKV_N * HD_N)];

// ---------------------------------------------------------------------------
// fused fp32 -> fp16 conversion over 5 segments
// ---------------------------------------------------------------------------
#define SEG_BIG   (4096 * 4096 / 4)
#define SEG_SMALL (1024 * 4096 / 4)
#define N4_TOTAL  (3 * SEG_BIG + 2 * SEG_SMALL)

__global__ void conv_all_f16(const float* __restrict__ X0, __half* __restrict__ H0,
                             const float* __restrict__ X1, __half* __restrict__ H1,
                             const float* __restrict__ X2, __half* __restrict__ H2,
                             const float* __restrict__ X3, __half* __restrict__ H3,
                             const float* __restrict__ X4, __half* __restrict__ H4) {
    int i = blockIdx.x * blockDim.x + threadIdx.x;
    if (i >= N4_TOTAL) return;
    const float* X;
    __half* H;
    int off = i;
    if (off < SEG_BIG)                    { X = X0; H = H0; }
    else if ((off -= SEG_BIG) < SEG_BIG)  { X = X1; H = H1; }
    else if ((off -= SEG_BIG) < SEG_SMALL){ X = X2; H = H2; }
    else if ((off -= SEG_SMALL) < SEG_SMALL){ X = X3; H = H3; }
    else { off -= SEG_SMALL; X = X4; H = H4; }
    float4 x = *(const float4*)(X + (size_t)off * 4);
    __half2* Hp = (__half2*)(H + (size_t)off * 4);
    Hp[0] = __half2(__float2half_rn(x.x), __float2half_rn(x.y));
    Hp[1] = __half2(__float2half_rn(x.z), __float2half_rn(x.w));
}

// ---------------------------------------------------------------------------
// K/V prep: RoPE K -> fp16, V -> fp16
// ---------------------------------------------------------------------------
__global__ void kv_prep(const float* __restrict__ K, const float* __restrict__ V,
                        const float* __restrict__ cosb, const float* __restrict__ sinb,
                        __half* __restrict__ Kf, __half* __restrict__ Vf) {
    int idx = blockIdx.x * blockDim.x + threadIdx.x;
    if (idx >= MROWS * HKV_N * 64) return;
    int d = idx & 63;
    int h = (idx >> 6) & 7;
    int bs = idx >> 9;
    int s = bs & (S_LEN - 1);
    float c  = cosb[s * HD_N + 64 + d];
    float sn = sinb[s * HD_N + 64 + d];
    size_t base = (size_t)bs * (HKV_N * HD_N) + h * HD_N + d;
    float x1 = K[base], x2 = K[base + 64];
    Kf[base]      = __float2half_rn(x1 * c - x2 * sn);
    Kf[base + 64] = __float2half_rn(x2 * c + x1 * sn);
    Vf[base]      = __float2half_rn(V[base]);
    Vf[base + 64] = __float2half_rn(V[base + 64]);
}

// ---------------------------------------------------------------------------
// fp16 GEMM body (R13-exact): 128x128 tile, BK=64, double-buffered
// ---------------------------------------------------------------------------
#define SROW   144
#define ATILE  (128 * SROW)
#define STAGE  (2 * ATILE)
#define SM_GEMM (2 * STAGE)
#define NCHUNK (KDIM / 64)

__device__ __forceinline__ void gemm_body(
    const __half* __restrict__ A, const __half* __restrict__ B,
    float* __restrict__ C, int Nn, int m0, int n0, char* smem) {
    const uint32_t smb = smem_u32(smem);
    const int tid = threadIdx.x;
    const int wid = tid >> 5;
    const int lane = tid & 31;
    const int wm = (wid >> 2) << 6;
    const int wn = (wid & 3) << 5;

    const __half* srcs[2] = { A + (size_t)m0 * KDIM, B + (size_t)n0 * KDIM };

    int r_ld[4], sseg[4];
#pragma unroll
    for (int i = 0; i < 4; i++) {
        int slot = tid + (i << 8);
        r_ld[i] = slot >> 3;
        sseg[i] = (slot & 7) << 3;
    }

    float acc[4][4][4];
#pragma unroll
    for (int i = 0; i < 4; i++)
#pragma unroll
        for (int j = 0; j < 4; j++)
#pragma unroll
            for (int t = 0; t < 4; t++) acc[i][j][t] = 0.f;

#pragma unroll
    for (int arr = 0; arr < 2; arr++) {
        char* dst = smem + arr * ATILE;
        const __half* src = srcs[arr];
#pragma unroll
        for (int i = 0; i < 4; i++)
            *(uint4*)(dst + r_ld[i] * SROW + (sseg[i] << 1)) =
                *(const uint4*)(src + (size_t)r_ld[i] * KDIM + sseg[i]);
    }
    __syncthreads();

    const uint32_t a_lrow = (lane & 15);
    const uint32_t a_lkh  = (lane >> 4) << 4;
    const uint32_t b_lrow = (lane & 7) + ((lane >> 4) << 3);
    const uint32_t b_lkh  = ((lane >> 3) & 1) << 4;

    uint4 regs[8];

    for (int c = 0; c < NCHUNK; c++) {
        const int s = c & 1;
        const uint32_t sb = smb + s * STAGE;
        const bool more = (c + 1 < NCHUNK);
        if (more) {
            const int k0 = (c + 1) << 6;
#pragma unroll
            for (int arr = 0; arr < 2; arr++)
#pragma unroll
                for (int i = 0; i < 4; i++)
                    regs[arr * 4 + i] =
                        *(const uint4*)(srcs[arr] + (size_t)r_ld[i] * KDIM + k0 + sseg[i]);
        }

#pragma unroll
        for (int ks = 0; ks < 4; ks++) {
            const uint32_t ko = ks << 5;
            uint32_t af[4][4];
#pragma unroll
            for (int i = 0; i < 4; i++) {
                uint32_t rowb = (wm + (i << 4) + a_lrow) * SROW + ko + a_lkh;
                ldm_x4(af[i], sb + 0 * ATILE + rowb);
            }
            uint32_t bf[2][4];
#pragma unroll
            for (int j2 = 0; j2 < 2; j2++) {
                uint32_t rowb = (wn + (j2 << 4) + b_lrow) * SROW + ko + b_lkh;
                ldm_x4(bf[j2], sb + 1 * ATILE + rowb);
            }
#pragma unroll
            for (int i = 0; i < 4; i++)
#pragma unroll
                for (int j = 0; j < 4; j++) {
                    const uint32_t* bb = &bf[j >> 1][(j & 1) << 1];
                    mma_f16(acc[i][j], af[i], bb[0], bb[1]);
                }
        }

        if (more) {
            const int so = (s ^ 1) * STAGE;
#pragma unroll
            for (int arr = 0; arr < 2; arr++)
#pragma unroll
                for (int i = 0; i < 4; i++)
                    *(uint4*)(smem + so + arr * ATILE + r_ld[i] * SROW + (sseg[i] << 1)) =
                        regs[arr * 4 + i];
        }
        __syncthreads();
    }

    const int erow = m0 + wm + (lane >> 2);
    const int ecol = n0 + wn + ((lane & 3) << 1);
#pragma unroll
    for (int i = 0; i < 4; i++) {
#pragma unroll
        for (int j = 0; j < 4; j++) {
            float* p0 = C + (size_t)(erow + (i << 4)) * Nn + ecol + (j << 3);
            float* p1 = p0 + (size_t)8 * Nn;
            *(float2*)p0 = make_float2(acc[i][j][0], acc[i][j][1]);
            *(float2*)p1 = make_float2(acc[i][j][2], acc[i][j][3]);
        }
    }
}

// Fused QKV projection
__global__ void __launch_bounds__(256, 1) gemm_qkv(
    const __half* __restrict__ hid,
    const __half* __restrict__ Wq, const __half* __restrict__ Wk,
    const __half* __restrict__ Wv,
    float* __restrict__ Cq, float* __restrict__ Ck, float* __restrict__ Cv) {
    extern __shared__ char smem[];
    const int nt = blockIdx.x;
    const int m0 = blockIdx.y << 7;
    const __half* B;
    float* C;
    int Nn, n0;
    if (nt < 32)      { B = Wq; C = Cq; Nn = 4096; n0 = nt << 7; }
    else if (nt < 40) { B = Wk; C = Ck; Nn = 1024; n0 = (nt - 32) << 7; }
    else              { B = Wv; C = Cv; Nn = 1024; n0 = (nt - 40) << 7; }
    gemm_body(hid, B, C, Nn, m0, n0, smem);
}

__global__ void __launch_bounds__(256, 1) gemm_f16(
    const __half* __restrict__ A, const __half* __restrict__ B,
    float* __restrict__ C, int Nn) {
    extern __shared__ char smem[];
    gemm_body(A, B, C, Nn, blockIdx.y << 7, blockIdx.x << 7, smem);
}

// ---------------------------------------------------------------------------
// Tensor-core attention — single change: __launch_bounds__(256, 2)
// (2 CTAs/SM: cross-CTA latency hiding for the barrier-separated phases)
// ---------------------------------------------------------------------------
#define QKV_RS 136
#define P_RS   72
#define SM_QF  0
#define SM_KF  17408
#define SM_VF  34816
#define SM_PF  52224
#define SM_RS  61440
#define SM_ATTN (SM_RS + 512)

__global__ void __launch_bounds__(256, 2) attn_tc(
    const float* __restrict__ Q,
    const __half* __restrict__ Kf, const __half* __restrict__ Vf,
    const float* __restrict__ cosb, const float* __restrict__ sinb,
    __half* __restrict__ Oh) {
    extern __shared__ char smem[];
    const uint32_t smb = smem_u32(smem);
    const int tid = threadIdx.x;
    const int wid = tid >> 5;
    const int lane = tid & 31;
    const int b   = blockIdx.x >> 5;
    const int h   = blockIdx.x & 31;
    const int kvh = h >> 2;
    const int q0  = blockIdx.y << 6;

    const uint32_t a_lrow = (lane & 15);
    const uint32_t a_lkh  = (lane >> 4) << 4;
    const uint32_t b_lrow = (lane & 7) + ((lane >> 4) << 3);
    const uint32_t b_lkh  = ((lane >> 3) & 1) << 4;
    const int wq = (wid & 3) << 4;
    const int wk = (wid >> 2) << 5;

#pragma unroll
    for (int it = 0; it < 4; it++) {
        int slot = tid + (it << 8);
        int r = slot >> 4;
        int d = (slot & 15) << 2;
        int srow = q0 + r;
        const float* src = Q + ((size_t)(b * S_LEN + srow)) * (HQ_N * HD_N) + h * HD_N + d;
        float4 x1 = *(const float4*)(src);
        float4 x2 = *(const float4*)(src + 64);
        float4 cs = *(const float4*)(cosb + srow * HD_N + 64 + d);
        float4 sn = *(const float4*)(sinb + srow * HD_N + 64 + d);
        __half* qf = (__half*)(smem + SM_QF) + r * QKV_RS;
        qf[d + 0] = __float2half_rn((x1.x * cs.x - x2.x * sn.x) * ATTN_SCALE);
        qf[d + 1] = __float2half_rn((x1.y * cs.y - x2.y * sn.y) * ATTN_SCALE);
        qf[d + 2] = __float2half_rn((x1.z * cs.z - x2.z * sn.z) * ATTN_SCALE);
        qf[d + 3] = __float2half_rn((x1.w * cs.w - x2.w * sn.w) * ATTN_SCALE);
        qf[d + 64] = __float2half_rn((x2.x * cs.x + x1.x * sn.x) * ATTN_SCALE);
        qf[d + 65] = __float2half_rn((x2.y * cs.y + x1.y * sn.y) * ATTN_SCALE);
        qf[d + 66] = __float2half_rn((x2.z * cs.z + x1.z * sn.z) * ATTN_SCALE);
        qf[d + 67] = __float2half_rn((x2.w * cs.w + x1.w * sn.w) * ATTN_SCALE);
    }

    float oacc[4][2][4];
#pragma unroll
    for (int i = 0; i < 4; i++)
#pragma unroll
        for (int j = 0; j < 2; j++)
#pragma unroll
            for (int t = 0; t < 4; t++) oacc[i][j][t] = 0.f;
    float rs0 = 0.f, rs1 = 0.f;

    const __half* kvsrc[2] = { Kf, Vf };
    const uint32_t kvdst[2] = { SM_KF, SM_VF };

    for (int kt = 0; kt < S_LEN; kt += 64) {
        __syncthreads();

#pragma unroll
        for (int arr = 0; arr < 2; arr++) {
            const __half* src = kvsrc[arr]
                + ((size_t)(b * S_LEN + kt)) * (HKV_N * HD_N) + kvh * HD_N;
            char* dst = smem + kvdst[arr];
#pragma unroll
            for (int it = 0; it < 4; it++) {
                int slot = tid + (it << 8);
                int r = slot >> 4;
                int cs = slot & 15;
                *(uint4*)(dst + r * (QKV_RS * 2) + (cs << 4)) =
                    *(const uint4*)(src + (size_t)r * (HKV_N * HD_N) + (cs << 3));
            }
        }
        __syncthreads();

        float sacc[4][4];
#pragma unroll
        for (int i = 0; i < 4; i++)
#pragma unroll
            for (int t = 0; t < 4; t++) sacc[i][t] = 0.f;

#pragma unroll
        for (int ks = 0; ks < 8; ks++) {
            const uint32_t ko = ks << 5;
            uint32_t aq[4];
            {
                uint32_t rowb = (wq + a_lrow) * (QKV_RS * 2) + ko + a_lkh;
                ldm_x4(aq, smb + SM_QF + rowb);
            }
            uint32_t bk[2][4];
#pragma unroll
            for (int g = 0; g < 2; g++) {
                uint32_t rowb = (wk + (g << 4) + b_lrow) * (QKV_RS * 2) + ko + b_lkh;
                ldm_x4(bk[g], smb + SM_KF + rowb);
            }
#pragma unroll
            for (int g = 0; g < 2; g++)
#pragma unroll
                for (int sub = 0; sub < 2; sub++) {
                    int nidx = (g << 1) + sub;
                    const uint32_t* kk = &bk[g][sub << 1];
                    mma_f16(sacc[nidx], aq, kk[0], kk[1]);
                }
        }

        float ps0 = 0.f, ps1 = 0.f;
        const int prow0 = wq + (lane >> 2);
#pragma unroll
        for (int f = 0; f < 4; f++) {
            float p0 = __expf(sacc[f][0]);
            float p1 = __expf(sacc[f][1]);
            float p2 = __expf(sacc[f][2]);
            float p3 = __expf(sacc[f][3]);
            ps0 += p0 + p1;
            ps1 += p2 + p3;
            int col = wk + (f << 3) + ((lane & 3) << 1);
            *(__half2*)((__half*)(smem + SM_PF) + prow0 * P_RS + col) =
                __half2(__float2half_rn(p0), __float2half_rn(p1));
            *(__half2*)((__half*)(smem + SM_PF) + (prow0 + 8) * P_RS + col) =
                __half2(__float2half_rn(p2), __float2half_rn(p3));
        }
        ps0 += __shfl_xor_sync(0xFFFFFFFF, ps0, 1);
        ps0 += __shfl_xor_sync(0xFFFFFFFF, ps0, 2);
        ps1 += __shfl_xor_sync(0xFFFFFFFF, ps1, 1);
        ps1 += __shfl_xor_sync(0xFFFFFFFF, ps1, 2);
        rs0 += ps0;
        rs1 += ps1;
        __syncthreads();

        const int nb = wid << 4;
#pragma unroll
        for (int ks = 0; ks < 4; ks++) {
            uint32_t vbf[4];
            {
                uint32_t rowb = ((ks << 4) + (lane & 15)) * (QKV_RS * 2) + ((nb + ((lane >> 4) << 3)) << 1);
                ldm_x4_t(vbf, smb + SM_VF + rowb);
            }
#pragma unroll
            for (int mt = 0; mt < 4; mt++) {
                uint32_t pf[4];
                uint32_t rowb = ((mt << 4) + a_lrow) * (P_RS * 2) + (ks << 5) + a_lkh;
                ldm_x4(pf, smb + SM_PF + rowb);
#pragma unroll
                for (int sub = 0; sub < 2; sub++) {
                    const uint32_t* vv = &vbf[sub << 1];
                    mma_f16(oacc[mt][sub], pf, vv[0], vv[1]);
                }
            }
        }
    }

    float* rssm = (float*)(smem + SM_RS);
    if ((lane & 3) == 0) {
        rssm[((wid >> 2) << 6) + wq + (lane >> 2)] = rs0;
        rssm[((wid >> 2) << 6) + wq + (lane >> 2) + 8] = rs1;
    }
    __syncthreads();

#pragma unroll
    for (int mt = 0; mt < 4; mt++) {
        int r0 = (mt << 4) + (lane >> 2);
        int r1 = r0 + 8;
        float inv0 = 1.0f / (rssm[r0] + rssm[64 + r0]);
        float inv1 = 1.0f / (rssm[r1] + rssm[64 + r1]);
#pragma unroll
        for (int sub = 0; sub < 2; sub++) {
            int col = (wid << 4) + (sub << 3) + ((lane & 3) << 1);
            float v00 = oacc[mt][sub][0] * inv0;
            float v01 = oacc[mt][sub][1] * inv0;
            float v10 = oacc[mt][sub][2] * inv1;
            float v11 = oacc[mt][sub][3] * inv1;
            size_t base0 = ((size_t)(b * S_LEN + q0 + r0)) * D_MODEL + h * HD_N + col;
            size_t base1 = ((size_t)(b * S_LEN + q0 + r1)) * D_MODEL + h * HD_N + col;
            *(__half2*)(Oh + base0) = __half2(__float2half_rn(v00), __float2half_rn(v01));
            *(__half2*)(Oh + base1) = __half2(__float2half_rn(v10), __float2half_rn(v11));
        }
    }
}

// ---------------------------------------------------------------------------
// Launch
// ---------------------------------------------------------------------------
extern "C" void kernel_launch(void* const* d_in, const int* in_sizes, int n_in,
                              void* d_out, int out_size) {
    const float* hidden = (const float*)d_in[0];
    const float* cosb   = (const float*)d_in[1];
    const float* sinb   = (const float*)d_in[2];
    const float* Wq     = (const float*)d_in[3];
    const float* Wk     = (const float*)d_in[4];
    const float* Wv     = (const float*)d_in[5];
    const float* Wo     = (const float*)d_in[6];
    float* out = (float*)d_out;

    float *pQ, *pK, *pV;
    cudaGetSymbolAddress((void**)&pQ, g_Q);
    cudaGetSymbolAddress((void**)&pK, g_K);
    cudaGetSymbolAddress((void**)&pV, g_V);

    __half *hid, *wq, *wk, *wv, *wo, *att, *pkf, *pvf;
    cudaGetSymbolAddress((void**)&hid, g_hid);
    cudaGetSymbolAddress((void**)&wq, g_wq);   cudaGetSymbolAddress((void**)&wk, g_wk);
    cudaGetSymbolAddress((void**)&wv, g_wv);   cudaGetSymbolAddress((void**)&wo, g_wo);
    cudaGetSymbolAddress((void**)&att, g_att);
    cudaGetSymbolAddress((void**)&pkf, g_kf);  cudaGetSymbolAddress((void**)&pvf, g_vf);

    conv_all_f16<<<(N4_TOTAL + 255) / 256, 256>>>(
        hidden, hid, Wq, wq, Wk, wk, Wv, wv, Wo, wo);

    cudaFuncSetAttribute(gemm_qkv, cudaFuncAttributeMaxDynamicSharedMemorySize, SM_GEMM);
    cudaFuncSetAttribute(gemm_f16, cudaFuncAttributeMaxDynamicSharedMemorySize, SM_GEMM);
    gemm_qkv<<<dim3(48, 32), 256, SM_GEMM>>>(hid, wq, wk, wv, pQ, pK, pV);

    {
        int tot = MROWS * HKV_N * 64;
        kv_prep<<<(tot + 255) / 256, 256>>>(pK, pV, cosb, sinb, pkf, pvf);
    }

    cudaFuncSetAttribute(attn_tc, cudaFuncAttributeMaxDynamicSharedMemorySize, SM_ATTN);
    attn_tc<<<dim3(B_N * HQ_N, S_LEN / 64), 256, SM_ATTN>>>(
        pQ, pkf, pvf, cosb, sinb, att);

    gemm_f16<<<dim3(32, 32), 256, SM_GEMM>>>(att, wo, out, 4096);
}